// round 10
// baseline (speedup 1.0000x reference)
#include <cuda_runtime.h>

// Fused: ConvTranspose3d(3->16, k=3, s=2, p=1, out_pad=1) + bias + MaxPool3d(2)
//        + softmax(ch) - subtract, swish, max(ch).
// x: [4,3,64,64,64] f32, w: [3,16,3,3,3], b: [16], subtract: [16] -> out [4,64,64,64]
//
// Lane c=lane&15 owns channel c; half=lane>>4 owns one of 2 adjacent-w voxels.
// R10: ALL 81 weights live in conflict-free smem (w4[pair][channel] float4
// triples; lanes 0..15 read 16 consecutive float4 = 2 wavefronts, verified
// correct + conflict-free in R9). Zero weight registers -> natural demand
// ~75-80 regs -> __launch_bounds__(128,6) without spilling -> 24 warps/SM.
// Comb-outer loop: each weight triple loaded once per batch (27 LDS.128),
// feeds 12 FMAs. x tile (parity-split float4) and no-max-pass epilogue kept.

#define N_BATCH 4
#define CIN 3
#define COUT 16
#define DIM 64

// pair r (0..8) within a cin, grouped by comb type t = dd*2+hh:
//  t0 (dd0,hh0): (kd,kh) = (1,1)(1,2)(2,1)(2,2)  -> r 0..3
//  t1 (dd0,hh1): (1,0)(2,0)                       -> r 4..5
//  t2 (dd1,hh0): (0,1)(0,2)                       -> r 6..7
//  t3 (dd1,hh1): (0,0)                            -> r 8
__device__ const int g_kd_of[9] = {1, 1, 2, 2, 1, 2, 0, 0, 0};
__device__ const int g_kh_of[9] = {1, 2, 1, 2, 0, 0, 1, 2, 0};

__global__ __launch_bounds__(128, 6) void fused_ctmp_softswish_kernel(
    const float* __restrict__ x,
    const float* __restrict__ wgt,
    const float* __restrict__ bias_g,
    const float* __restrict__ sub_g,
    float* __restrict__ out)
{
    // x tile: tile[warp][comb][p][q] = {x_row[4q+p], +1, +2, +3}
    __shared__ float4 tile[4][12][2][16];
    // weights: w4sm[pair 0..26][channel] = {w[kw=0], w[kw=1], w[kw=2], 0}
    __shared__ float4 w4sm[27][16];

    const int tid  = threadIdx.x;
    const int lane = tid & 31;
    const int wid  = tid >> 5;
    const int c    = lane & 15;
    const int half = lane >> 4;

    // ---- one-time: pack all 81 weights into smem (channel-contiguous) ----
    for (int idx = tid; idx < 27 * 16; idx += 128) {
        const int p   = idx >> 4;   // pair 0..26
        const int cc  = idx & 15;   // channel
        const int cin = p / 9;
        const int r   = p % 9;
        const int kd  = g_kd_of[r];
        const int kh  = g_kh_of[r];
        const int gb  = (((cin * COUT + cc) * 3 + kd) * 3 + kh) * 3;
        w4sm[p][cc] = make_float4(__ldg(&wgt[gb + 0]),
                                  __ldg(&wgt[gb + 1]),
                                  __ldg(&wgt[gb + 2]), 0.f);
    }
    const float bias = __ldg(&bias_g[c]);
    const float subc = __ldg(&sub_g[c]);
    __syncthreads();

    // comb-type tables: number of pairs and offset of r within the cin group
    const int PCNT[4] = {4, 2, 2, 1};
    const int POFF[4] = {0, 4, 6, 8};

    const int gwarp  = blockIdx.x * 4 + wid;
    const int nwarps = gridDim.x * 4;
    const int nrows  = N_BATCH * DIM * DIM;

    const int bp = lane >> 4;
    const int bq = lane & 15;

    for (int row = gwarp; row < nrows; row += nwarps) {
        const int h = row & 63;
        const int d = (row >> 6) & 63;
        const int n = row >> 12;

        // ---- build parity-split float4 x tile ----
        #pragma unroll
        for (int comb = 0; comb < 12; ++comb) {
            const int cin = comb >> 2;
            const int dd  = (comb >> 1) & 1;
            const int hh  = comb & 1;
            const int dcur = d + dd;
            const int hcur = h + hh;
            const bool rowok = (dcur < DIM) && (hcur < DIM);
            const float* src = x + (((n * CIN + cin) * DIM + dcur) * DIM + hcur) * DIM;
            const int base = 4 * bq + bp;
            float a0 = 0.f, a1 = 0.f, a2 = 0.f, a3 = 0.f;
            if (rowok) {
                a0 = __ldg(&src[base]);
                a1 = __ldg(&src[base + 1]);
                a2 = __ldg(&src[base + 2]);
                if (base + 3 < DIM) a3 = __ldg(&src[base + 3]);
            }
            tile[wid][comb][bp][bq] = make_float4(a0, a1, a2, a3);
        }
        __syncwarp();

        float* orow = out + ((n * DIM + d) * DIM + h) * DIM;

        for (int w0 = 0; w0 < DIM; w0 += 8) {
            const int q0 = w0 >> 2;

            // acc[jp*2+jj][pd*4+ph*2+pw]
            float acc[4][8];
            #pragma unroll
            for (int j = 0; j < 4; ++j)
                #pragma unroll
                for (int i = 0; i < 8; ++i) acc[j][i] = 0.f;

            #pragma unroll
            for (int comb = 0; comb < 12; ++comb) {
                const int cin = comb >> 2;
                const int t   = comb & 3;
                const int np  = PCNT[t];
                const int po  = POFF[t];

                const float4 v0 = tile[wid][comb][half][q0];
                const float4 v1 = tile[wid][comb][half][q0 + 1];
                // x[wv] per (jp,jj):   jp0: {v0.x, v0.z}, jp1: {v1.x, v1.z}
                // x[wv+1] per (jp,jj): jp0: {v0.y, v0.w}, jp1: {v1.y, v1.w}
                const float xA[4] = {v0.x, v0.z, v1.x, v1.z};  // index jp*2+jj
                const float xB[4] = {v0.y, v0.w, v1.y, v1.w};

                #pragma unroll
                for (int i = 0; i < 4; ++i) {
                    if (i >= np) continue;
                    const float4 wq = w4sm[cin * 9 + po + i][c];
                    const int pd = (t == 0) ? (i >> 1) : (t == 1) ? i : 1;
                    const int ph = (t == 0) ? (i & 1)  : (t == 2) ? i : 1;
                    const int a0i = pd * 4 + ph * 2;   // pw=0
                    const int a1i = a0i + 1;           // pw=1
                    #pragma unroll
                    for (int j = 0; j < 4; ++j) {
                        acc[j][a0i] = fmaf(wq.y, xA[j], acc[j][a0i]);
                        acc[j][a1i] = fmaf(wq.z, xA[j], acc[j][a1i]);
                        acc[j][a1i] = fmaf(wq.x, xB[j], acc[j][a1i]);
                    }
                }
            }

            // ---- maxpool over 8 candidates + bias ----
            float m[4];
            #pragma unroll
            for (int j = 0; j < 4; ++j) {
                const float* a = acc[j];
                float mm = fmaxf(fmaxf(fmaxf(a[0], a[1]), fmaxf(a[2], a[3])),
                                 fmaxf(fmaxf(a[4], a[5]), fmaxf(a[6], a[7])));
                m[j] = mm + bias;
            }

            // ---- epilogue: no softmax max-pass; 2 chains interleaved (ILP=4) ----
            float e[4], sum[4];
            #pragma unroll
            for (int j = 0; j < 4; ++j) { e[j] = __expf(m[j]); sum[j] = e[j]; }
            #pragma unroll
            for (int s = 1; s < 16; s <<= 1) {
                #pragma unroll
                for (int j = 0; j < 4; ++j)
                    sum[j] += __shfl_xor_sync(0xffffffffu, sum[j], s);
            }

            float r[4];
            #pragma unroll
            for (int j = 0; j < 4; ++j) {
                const float sft = __fdividef(e[j], sum[j]);
                const float z   = sft - subc;
                r[j] = __fdividef(z, 1.f + __expf(-z));   // swish
            }
            #pragma unroll
            for (int s = 1; s < 16; s <<= 1) {
                #pragma unroll
                for (int j = 0; j < 4; ++j)
                    r[j] = fmaxf(r[j], __shfl_xor_sync(0xffffffffu, r[j], s));
            }

            if (c == 0) {
                #pragma unroll
                for (int j = 0; j < 4; ++j)
                    orow[w0 + 2 * j + half] = r[j];
            }
        }
        __syncwarp();
    }
}

extern "C" void kernel_launch(void* const* d_in, const int* in_sizes, int n_in,
                              void* d_out, int out_size) {
    const float* x   = (const float*)d_in[0];
    const float* w   = (const float*)d_in[1];
    const float* b   = (const float*)d_in[2];
    const float* sub = (const float*)d_in[3];
    float* out = (float*)d_out;
    (void)in_sizes; (void)n_in; (void)out_size;
    fused_ctmp_softswish_kernel<<<2048, 128>>>(x, w, b, sub, out);
}

// round 11
// speedup vs baseline: 1.9302x; 1.9302x over previous
#include <cuda_runtime.h>

// Fused: ConvTranspose3d(3->16, k=3, s=2, p=1, out_pad=1) + bias + MaxPool3d(2)
//        + softmax(ch) - subtract, swish, max(ch).
// x: [4,3,64,64,64] f32, w: [3,16,3,3,3], b: [16], subtract: [16] -> out [4,64,64,64]
//
// Lane c=lane&15 owns channel c; half=lane>>4 owns one of 2 adjacent-w voxels.
// R11: R5 structure (81 reg weights, parity-split float4 x tile, 4 blocks/SM)
// + software-pipelined epilogue: batch i's softmax/swish/max chains execute in
// the same basic block as batch i+1's 324-FMA compute, so ptxas fills the
// SHFL/MUFU latency with FMA issues instead of stalling.

#define N_BATCH 4
#define CIN 3
#define COUT 16
#define DIM 64

__device__ __forceinline__ void conv_batch(
    const float4 (*tw)[2][16],   // tile[wid]: [comb][parity][q]
    int half, int q0,
    const float* __restrict__ wr, float bias,
    float m[4])
{
    // parity tap tables: even conv pos -> k=1 @ off0; odd -> k=2 @ off0, k=0 @ off1
    const int NP[2]      = {1, 2};
    const int KTAP[2][2] = {{1, 0}, {2, 0}};
    const int XOFF[2][2] = {{0, 0}, {0, 1}};

    #pragma unroll
    for (int jp = 0; jp < 2; ++jp) {
        float acc[2][8];
        #pragma unroll
        for (int jj = 0; jj < 2; ++jj)
            #pragma unroll
            for (int i = 0; i < 8; ++i) acc[jj][i] = 0.f;

        #pragma unroll
        for (int comb = 0; comb < 12; ++comb) {
            const int cin = comb >> 2;
            const int dd  = (comb >> 1) & 1;
            const int hh  = comb & 1;
            const float4 v = tw[comb][half][q0 + jp];
            const float xxs[2][2] = {{v.x, v.y}, {v.z, v.w}};

            #pragma unroll
            for (int pd = 0; pd < 2; ++pd) {
                #pragma unroll
                for (int jd = 0; jd < 2; ++jd) {
                    if (jd >= NP[pd] || XOFF[pd][jd] != dd) continue;
                    const int kd = KTAP[pd][jd];
                    #pragma unroll
                    for (int ph = 0; ph < 2; ++ph) {
                        #pragma unroll
                        for (int jh = 0; jh < 2; ++jh) {
                            if (jh >= NP[ph] || XOFF[ph][jh] != hh) continue;
                            const int kh = KTAP[ph][jh];
                            #pragma unroll
                            for (int pw = 0; pw < 2; ++pw) {
                                #pragma unroll
                                for (int jw = 0; jw < 2; ++jw) {
                                    if (jw >= NP[pw]) continue;
                                    const int kw = KTAP[pw][jw];
                                    const float wv_ = wr[cin * 27 + kd * 9 + kh * 3 + kw];
                                    const int ww = XOFF[pw][jw];
                                    #pragma unroll
                                    for (int jj = 0; jj < 2; ++jj)
                                        acc[jj][pd * 4 + ph * 2 + pw] =
                                            fmaf(wv_, xxs[jj][ww], acc[jj][pd * 4 + ph * 2 + pw]);
                                }
                            }
                        }
                    }
                }
            }
        }

        #pragma unroll
        for (int jj = 0; jj < 2; ++jj) {
            const float* a = acc[jj];
            float mm = fmaxf(fmaxf(fmaxf(a[0], a[1]), fmaxf(a[2], a[3])),
                             fmaxf(fmaxf(a[4], a[5]), fmaxf(a[6], a[7])));
            m[2 * jp + jj] = mm + bias;
        }
    }
}

__device__ __forceinline__ void epilogue4(
    const float m[4], float subc, int c, int half, float* orow, int w0)
{
    float e[4], sum[4];
    #pragma unroll
    for (int j = 0; j < 4; ++j) { e[j] = __expf(m[j]); sum[j] = e[j]; }
    #pragma unroll
    for (int s = 1; s < 16; s <<= 1) {
        #pragma unroll
        for (int j = 0; j < 4; ++j)
            sum[j] += __shfl_xor_sync(0xffffffffu, sum[j], s);
    }

    float r[4];
    #pragma unroll
    for (int j = 0; j < 4; ++j) {
        const float sft = __fdividef(e[j], sum[j]);
        const float z   = sft - subc;
        r[j] = __fdividef(z, 1.f + __expf(-z));   // swish
    }
    #pragma unroll
    for (int s = 1; s < 16; s <<= 1) {
        #pragma unroll
        for (int j = 0; j < 4; ++j)
            r[j] = fmaxf(r[j], __shfl_xor_sync(0xffffffffu, r[j], s));
    }

    if (c == 0) {
        #pragma unroll
        for (int j = 0; j < 4; ++j)
            orow[w0 + 2 * j + half] = r[j];
    }
}

__global__ __launch_bounds__(128, 4) void fused_ctmp_softswish_kernel(
    const float* __restrict__ x,
    const float* __restrict__ wgt,
    const float* __restrict__ bias_g,
    const float* __restrict__ sub_g,
    float* __restrict__ out)
{
    __shared__ float4 tile[4][12][2][16];

    const int lane = threadIdx.x & 31;
    const int wid  = threadIdx.x >> 5;
    const int c    = lane & 15;
    const int half = lane >> 4;

    // weights for channel c (81 floats) in registers
    float wr[81];
    #pragma unroll
    for (int cin = 0; cin < CIN; ++cin) {
        #pragma unroll
        for (int k = 0; k < 27; ++k)
            wr[cin * 27 + k] = __ldg(&wgt[(cin * COUT + c) * 27 + k]);
    }
    const float bias = __ldg(&bias_g[c]);
    const float subc = __ldg(&sub_g[c]);

    const int gwarp  = blockIdx.x * 4 + wid;
    const int nwarps = gridDim.x * 4;
    const int nrows  = N_BATCH * DIM * DIM;

    const int bp = lane >> 4;
    const int bq = lane & 15;

    for (int row = gwarp; row < nrows; row += nwarps) {
        const int h = row & 63;
        const int d = (row >> 6) & 63;
        const int n = row >> 12;

        // ---- build parity-split float4 x tile ----
        #pragma unroll
        for (int comb = 0; comb < 12; ++comb) {
            const int cin = comb >> 2;
            const int dd  = (comb >> 1) & 1;
            const int hh  = comb & 1;
            const int dcur = d + dd;
            const int hcur = h + hh;
            const bool rowok = (dcur < DIM) && (hcur < DIM);
            const float* src = x + (((n * CIN + cin) * DIM + dcur) * DIM + hcur) * DIM;
            const int base = 4 * bq + bp;
            float a0 = 0.f, a1 = 0.f, a2 = 0.f, a3 = 0.f;
            if (rowok) {
                a0 = __ldg(&src[base]);
                a1 = __ldg(&src[base + 1]);
                a2 = __ldg(&src[base + 2]);
                if (base + 3 < DIM) a3 = __ldg(&src[base + 3]);
            }
            tile[wid][comb][bp][bq] = make_float4(a0, a1, a2, a3);
        }
        __syncwarp();

        float* orow = out + ((n * DIM + d) * DIM + h) * DIM;
        const float4 (*tw)[2][16] = tile[wid];

        // ---- software pipeline: epilogue of batch i under compute of i+1 ----
        float m_prev[4];
        conv_batch(tw, half, 0, wr, bias, m_prev);   // prologue: batch 0

        #pragma unroll 1
        for (int w0 = 8; w0 < DIM; w0 += 8) {
            float m_cur[4];
            conv_batch(tw, half, w0 >> 2, wr, bias, m_cur);   // 324 FMAs
            epilogue4(m_prev, subc, c, half, orow, w0 - 8);   // interleaved by ptxas
            #pragma unroll
            for (int j = 0; j < 4; ++j) m_prev[j] = m_cur[j];
        }
        epilogue4(m_prev, subc, c, half, orow, DIM - 8);      // tail: batch 7

        __syncwarp();
    }
}

extern "C" void kernel_launch(void* const* d_in, const int* in_sizes, int n_in,
                              void* d_out, int out_size) {
    const float* x   = (const float*)d_in[0];
    const float* w   = (const float*)d_in[1];
    const float* b   = (const float*)d_in[2];
    const float* sub = (const float*)d_in[3];
    float* out = (float*)d_out;
    (void)in_sizes; (void)n_in; (void)out_size;
    fused_ctmp_softswish_kernel<<<2048, 128>>>(x, w, b, sub, out);
}

// round 12
// speedup vs baseline: 2.0578x; 1.0661x over previous
#include <cuda_runtime.h>

// Fused: ConvTranspose3d(3->16, k=3, s=2, p=1, out_pad=1) + bias + MaxPool3d(2)
//        + softmax(ch) - subtract, swish, max(ch).
// x: [4,3,64,64,64] f32, w: [3,16,3,3,3], b: [16], subtract: [16] -> out [4,64,64,64]
//
// Lane c=lane&15 owns channel c; half=lane>>4 owns one of 2 adjacent-w voxels.
// R12: byte-identical R5 kernel (81 reg weights, parity-split float4 x tile,
// ILP-4 batches, no-max-pass softmax) launched as an exact-fit persistent grid
// (4 blocks x numSMs = one wave, no wave-quantization tail; weight preload
// amortized over ~7 rows per warp instead of 2).

#define N_BATCH 4
#define CIN 3
#define COUT 16
#define DIM 64

__global__ __launch_bounds__(128, 4) void fused_ctmp_softswish_kernel(
    const float* __restrict__ x,
    const float* __restrict__ wgt,
    const float* __restrict__ bias_g,
    const float* __restrict__ sub_g,
    float* __restrict__ out)
{
    // tile[warp][comb][p][q] = {x_row[4q+p], +1, +2, +3}; comb = cin*4+dd*2+hh
    __shared__ float4 tile[4][12][2][16];

    const int lane = threadIdx.x & 31;
    const int wid  = threadIdx.x >> 5;
    const int c    = lane & 15;
    const int half = lane >> 4;

    // weights for channel c (81 floats) in registers
    float wr[81];
    #pragma unroll
    for (int cin = 0; cin < CIN; ++cin) {
        #pragma unroll
        for (int k = 0; k < 27; ++k)
            wr[cin * 27 + k] = __ldg(&wgt[(cin * COUT + c) * 27 + k]);
    }
    const float bias = __ldg(&bias_g[c]);
    const float subc = __ldg(&sub_g[c]);

    // parity tap tables: even conv pos -> k=1 @ off 0; odd -> k=2 @ off 0, k=0 @ off 1
    const int NP[2]      = {1, 2};
    const int KTAP[2][2] = {{1, 0}, {2, 0}};
    const int XOFF[2][2] = {{0, 0}, {0, 1}};

    const int gwarp  = blockIdx.x * 4 + wid;
    const int nwarps = gridDim.x * 4;
    const int nrows  = N_BATCH * DIM * DIM;

    const int bp = lane >> 4;
    const int bq = lane & 15;

    for (int row = gwarp; row < nrows; row += nwarps) {
        const int h = row & 63;
        const int d = (row >> 6) & 63;
        const int n = row >> 12;

        // ---- build parity-split float4 tile ----
        #pragma unroll
        for (int comb = 0; comb < 12; ++comb) {
            const int cin = comb >> 2;
            const int dd  = (comb >> 1) & 1;
            const int hh  = comb & 1;
            const int dcur = d + dd;
            const int hcur = h + hh;
            const bool rowok = (dcur < DIM) && (hcur < DIM);
            const float* src = x + (((n * CIN + cin) * DIM + dcur) * DIM + hcur) * DIM;
            const int base = 4 * bq + bp;
            float a0 = 0.f, a1 = 0.f, a2 = 0.f, a3 = 0.f;
            if (rowok) {
                a0 = __ldg(&src[base]);
                a1 = __ldg(&src[base + 1]);
                a2 = __ldg(&src[base + 2]);
                if (base + 3 < DIM) a3 = __ldg(&src[base + 3]);
            }
            tile[wid][comb][bp][bq] = make_float4(a0, a1, a2, a3);
        }
        __syncwarp();

        float* orow = out + ((n * DIM + d) * DIM + h) * DIM;

        for (int w0 = 0; w0 < DIM; w0 += 8) {
            const int q0 = w0 >> 2;
            float m[4];

            // ---- compute: 2 jp-groups x 2 voxel-pairs, comb-outer ----
            #pragma unroll
            for (int jp = 0; jp < 2; ++jp) {
                float acc[2][8];
                #pragma unroll
                for (int jj = 0; jj < 2; ++jj)
                    #pragma unroll
                    for (int i = 0; i < 8; ++i) acc[jj][i] = 0.f;

                #pragma unroll
                for (int comb = 0; comb < 12; ++comb) {
                    const int cin = comb >> 2;
                    const int dd  = (comb >> 1) & 1;
                    const int hh  = comb & 1;
                    const float4 v = tile[wid][comb][half][q0 + jp];
                    const float xxs[2][2] = {{v.x, v.y}, {v.z, v.w}};

                    #pragma unroll
                    for (int pd = 0; pd < 2; ++pd) {
                        #pragma unroll
                        for (int jd = 0; jd < 2; ++jd) {
                            if (jd >= NP[pd] || XOFF[pd][jd] != dd) continue;
                            const int kd = KTAP[pd][jd];
                            #pragma unroll
                            for (int ph = 0; ph < 2; ++ph) {
                                #pragma unroll
                                for (int jh = 0; jh < 2; ++jh) {
                                    if (jh >= NP[ph] || XOFF[ph][jh] != hh) continue;
                                    const int kh = KTAP[ph][jh];
                                    #pragma unroll
                                    for (int pw = 0; pw < 2; ++pw) {
                                        #pragma unroll
                                        for (int jw = 0; jw < 2; ++jw) {
                                            if (jw >= NP[pw]) continue;
                                            const int kw = KTAP[pw][jw];
                                            const float wv_ = wr[cin * 27 + kd * 9 + kh * 3 + kw];
                                            const int ww = XOFF[pw][jw];
                                            #pragma unroll
                                            for (int jj = 0; jj < 2; ++jj)
                                                acc[jj][pd * 4 + ph * 2 + pw] =
                                                    fmaf(wv_, xxs[jj][ww], acc[jj][pd * 4 + ph * 2 + pw]);
                                        }
                                    }
                                }
                            }
                        }
                    }
                }

                #pragma unroll
                for (int jj = 0; jj < 2; ++jj) {
                    const float* a = acc[jj];
                    float mm = fmaxf(fmaxf(fmaxf(a[0], a[1]), fmaxf(a[2], a[3])),
                                     fmaxf(fmaxf(a[4], a[5]), fmaxf(a[6], a[7])));
                    m[2 * jp + jj] = mm + bias;
                }
            }

            // ---- epilogue: no softmax max-pass; 2 chains interleaved (ILP=4) ----
            float e[4], sum[4];
            #pragma unroll
            for (int j = 0; j < 4; ++j) { e[j] = __expf(m[j]); sum[j] = e[j]; }
            #pragma unroll
            for (int s = 1; s < 16; s <<= 1) {
                #pragma unroll
                for (int j = 0; j < 4; ++j)
                    sum[j] += __shfl_xor_sync(0xffffffffu, sum[j], s);
            }

            float r[4];
            #pragma unroll
            for (int j = 0; j < 4; ++j) {
                const float sft = __fdividef(e[j], sum[j]);
                const float z   = sft - subc;
                r[j] = __fdividef(z, 1.f + __expf(-z));   // swish
            }
            #pragma unroll
            for (int s = 1; s < 16; s <<= 1) {
                #pragma unroll
                for (int j = 0; j < 4; ++j)
                    r[j] = fmaxf(r[j], __shfl_xor_sync(0xffffffffu, r[j], s));
            }

            if (c == 0) {
                #pragma unroll
                for (int j = 0; j < 4; ++j)
                    orow[w0 + 2 * j + half] = r[j];
            }
        }
        __syncwarp();
    }
}

extern "C" void kernel_launch(void* const* d_in, const int* in_sizes, int n_in,
                              void* d_out, int out_size) {
    const float* x   = (const float*)d_in[0];
    const float* w   = (const float*)d_in[1];
    const float* b   = (const float*)d_in[2];
    const float* sub = (const float*)d_in[3];
    float* out = (float*)d_out;
    (void)in_sizes; (void)n_in; (void)out_size;

    // exact-fit persistent grid: 4 resident blocks per SM, one wave
    int dev = 0, sms = 148;
    cudaGetDevice(&dev);
    cudaDeviceGetAttribute(&sms, cudaDevAttrMultiProcessorCount, dev);
    fused_ctmp_softswish_kernel<<<4 * sms, 128>>>(x, w, b, sub, out);
}